// round 15
// baseline (speedup 1.0000x reference)
#include <cuda_runtime.h>
#include <cstdint>
#include <cstddef>

// Scatter-mean message passing via single-pass padded-CSR build + per-node gather-reduce.
//   out[t] = mean over edges e with tgt[e]==t of x[src[e]]
// x: [N, 64] f32, edge_idx: [2, E] i32 (row 0 = src, row 1 = tgt)
//
// Scratch counters are SELF-RESETTING: zero at static init (first call), and
// the aggregate kernel restores them to zero every call -> no memset nodes.

#define F 64
#define MAX_N (1 << 17)      // >= 100000
#define SLOTS 32             // padded CSR row capacity = 128B = one L2 line
#define MAX_OVER 16384       // overflow spill capacity (correctness fallback)
#define AGG_BLOCKS (148 * 8) // persistent grid: one wave at occ 8

typedef unsigned long long ull;

__device__ int g_cnt[MAX_N];                     // per-node edge count (true degree)
__device__ int g_sorted[(size_t)MAX_N * SLOTS];  // per-node src BYTE OFFSETS (src*256)
__device__ int g_over_src[MAX_OVER];             // overflow: src byte offsets
__device__ int g_over_tgt[MAX_OVER];
__device__ int g_over_cnt[1];
__device__ unsigned int g_done;                  // aggregate block-completion ticket

__device__ __forceinline__ void spill_edge(int soff, int d) {
    int op = atomicAdd(&g_over_cnt[0], 1);
    if (op < MAX_OVER) { g_over_src[op] = soff; g_over_tgt[op] = d; }
}

// Scattered 4B store bypassing L1 (no reuse).
__device__ __forceinline__ void stg_cg32(int* p, int v) {
    asm volatile("st.global.cg.u32 [%0], %1;" :: "l"(p), "r"(v) : "memory");
}

// Single build pass: 2 edges per thread (int2 loads).
__global__ void fill_kernel(const int2* __restrict__ src2,
                            const int2* __restrict__ tgt2, int E2,
                            const int* __restrict__ src,
                            const int* __restrict__ tgt, int E) {
    int t = blockIdx.x * blockDim.x + threadIdx.x;
    if (t < E2) {
        int2 s = __ldg(&src2[t]);
        int2 d = __ldg(&tgt2[t]);
        int p0 = atomicAdd(&g_cnt[d.x], 1);
        int p1 = atomicAdd(&g_cnt[d.y], 1);
        if (p0 < SLOTS) stg_cg32(&g_sorted[(size_t)d.x * SLOTS + p0], s.x << 8);
        else spill_edge(s.x << 8, d.x);
        if (p1 < SLOTS) stg_cg32(&g_sorted[(size_t)d.y * SLOTS + p1], s.y << 8);
        else spill_edge(s.y << 8, d.y);
    }
    if (t == 0) {
        for (int e = E2 * 2; e < E; e++) {
            int d = tgt[e];
            int pos = atomicAdd(&g_cnt[d], 1);
            if (pos < SLOTS) stg_cg32(&g_sorted[(size_t)d * SLOTS + pos], src[e] << 8);
            else spill_edge(src[e] << 8, d);
        }
    }
}

__device__ __forceinline__ ull f2add(ull a, ull b) {
    ull r;
    asm("add.rn.f32x2 %0, %1, %2;" : "=l"(r) : "l"(a), "l"(b));
    return r;
}
__device__ __forceinline__ ull f2mul(ull a, ull b) {
    ull r;
    asm("mul.rn.f32x2 %0, %1, %2;" : "=l"(r) : "l"(a), "l"(b));
    return r;
}
// L2-only gather (skip L1 allocation: gathered rows have ~no per-SM reuse).
__device__ __forceinline__ ull ldg_cg64(const void* p) {
    ull r;
    asm volatile("ld.global.cg.u64 %0, [%1];" : "=l"(r) : "l"(p));
    return r;
}

// One warp per node, persistent grid-stride (one wave). Lane owns 8B (float2)
// of the 256B row. Unroll 2, one warp-uniform int2 idx load per edge pair,
// 2 accumulators (measured optimum vs L1tex queue contention).
// Epilogue: lane 0 zeroes g_cnt[n] (self-resetting scratch); the last block
// to finish zeroes g_over_cnt and the ticket itself.
__global__ void __launch_bounds__(256)
aggregate_kernel(const char* __restrict__ xbase,
                 float2* __restrict__ out2, int N) {
    int warp_id = (blockIdx.x * blockDim.x + threadIdx.x) >> 5;
    int lane = threadIdx.x & 31;
    int nwarps = (gridDim.x * blockDim.x) >> 5;
    const char* xlane = xbase + (lane << 3);

    for (int n = warp_id; n < N; n += nwarps) {
        int count = g_cnt[n];
        int m = count < SLOTS ? count : SLOTS;
        const int2* row2 = (const int2*)&g_sorted[(size_t)n * SLOTS];

        ull a0 = 0, a1 = 0;

        int k = 0;
        for (; k + 2 <= m; k += 2) {
            int2 s = __ldg(&row2[k >> 1]);
            ull v0 = ldg_cg64(xlane + (size_t)(unsigned)s.x);
            ull v1 = ldg_cg64(xlane + (size_t)(unsigned)s.y);
            a0 = f2add(a0, v0);
            a1 = f2add(a1, v1);
        }
        if (k < m) {
            int s = ((const int*)row2)[k];
            a0 = f2add(a0, ldg_cg64(xlane + (size_t)(unsigned)s));
        }

        // Overflow fallback (cold: only if some node's degree exceeded SLOTS).
        if (count > SLOTS) {
            int oc = g_over_cnt[0];
            for (int i = 0; i < oc; i++) {
                if (g_over_tgt[i] == n) {
                    int s = g_over_src[i];
                    a0 = f2add(a0, ldg_cg64(xlane + (size_t)(unsigned)s));
                }
            }
        }

        // Self-reset this node's counter for the next call.
        if (lane == 0) stg_cg32(&g_cnt[n], 0);

        a0 = f2add(a0, a1);

        float inv = count > 0 ? 1.0f / (float)count : 0.0f;
        ull inv2;
        asm("mov.b64 %0, {%1, %1};" : "=l"(inv2) : "f"(inv));
        ull o = f2mul(a0, inv2);

        unsigned int lo, hi;
        asm("mov.b64 {%0, %1}, %2;" : "=r"(lo), "=r"(hi) : "l"(o));
        float2 ov;
        ov.x = __uint_as_float(lo);
        ov.y = __uint_as_float(hi);
        out2[(size_t)n * 32 + lane] = ov;
    }

    // Last finishing block resets the overflow counter + ticket (after all
    // possible readers of the overflow list are done).
    __syncthreads();
    if (threadIdx.x == 0) {
        unsigned int done = atomicAdd(&g_done, 1u);
        if (done == gridDim.x - 1u) {
            g_over_cnt[0] = 0;
            g_done = 0u;
        }
    }
}

extern "C" void kernel_launch(void* const* d_in, const int* in_sizes, int n_in,
                              void* d_out, int out_size) {
    const float* x = (const float*)d_in[0];
    const int* edge_idx = (const int*)d_in[1];

    int E = in_sizes[1] / 2;
    int N = out_size / F;

    const int* src = edge_idx;       // row 0
    const int* tgt = edge_idx + E;   // row 1

    const int T = 256;

    int E2 = E / 2;
    int fill_blocks = (E2 + T - 1) / T;
    if (fill_blocks < 1) fill_blocks = 1;
    fill_kernel<<<fill_blocks, T>>>((const int2*)src, (const int2*)tgt, E2,
                                    src, tgt, E);

    // Persistent one-wave grid (cap at what N needs).
    long long warps_needed = (long long)N;
    long long blocks_needed = (warps_needed * 32 + T - 1) / T;
    int agg_blocks = blocks_needed < AGG_BLOCKS ? (int)blocks_needed : AGG_BLOCKS;
    aggregate_kernel<<<agg_blocks, T>>>((const char*)x, (float2*)d_out, N);
}

// round 16
// speedup vs baseline: 1.2883x; 1.2883x over previous
#include <cuda_runtime.h>
#include <cstdint>
#include <cstddef>

// Scatter-mean message passing via single-pass padded-CSR build + per-node gather-reduce.
//   out[t] = mean over edges e with tgt[e]==t of x[src[e]]
// x: [N, 64] f32, edge_idx: [2, E] i32 (row 0 = src, row 1 = tgt)
//
// Overflow counter lives at g_cnt[N] so ONE memset node zeroes all scratch.

#define F 64
#define MAX_N (1 << 17)      // >= 100000 (+1 slot for the overflow counter)
#define SLOTS 32             // padded CSR row capacity = 128B = one L2 line
#define MAX_OVER 16384       // overflow spill capacity (correctness fallback)
#define AGG_BLOCKS (148 * 8) // persistent grid: one wave at occ 8

typedef unsigned long long ull;

__device__ int g_cnt[MAX_N + 1];                 // [0..N): degrees; [N]: overflow cursor
__device__ int g_sorted[(size_t)MAX_N * SLOTS];  // per-node src BYTE OFFSETS (src*256)
__device__ int g_over_src[MAX_OVER];             // overflow: src byte offsets
__device__ int g_over_tgt[MAX_OVER];

__device__ __forceinline__ void spill_edge(int soff, int d, int N) {
    int op = atomicAdd(&g_cnt[N], 1);
    if (op < MAX_OVER) { g_over_src[op] = soff; g_over_tgt[op] = d; }
}

// Scattered 4B store bypassing L1 (no reuse).
__device__ __forceinline__ void stg_cg32(int* p, int v) {
    asm volatile("st.global.cg.u32 [%0], %1;" :: "l"(p), "r"(v) : "memory");
}

// Single build pass: 2 edges per thread (int2 loads).
__global__ void fill_kernel(const int2* __restrict__ src2,
                            const int2* __restrict__ tgt2, int E2,
                            const int* __restrict__ src,
                            const int* __restrict__ tgt, int E, int N) {
    int t = blockIdx.x * blockDim.x + threadIdx.x;
    if (t < E2) {
        int2 s = __ldg(&src2[t]);
        int2 d = __ldg(&tgt2[t]);
        int p0 = atomicAdd(&g_cnt[d.x], 1);
        int p1 = atomicAdd(&g_cnt[d.y], 1);
        if (p0 < SLOTS) stg_cg32(&g_sorted[(size_t)d.x * SLOTS + p0], s.x << 8);
        else spill_edge(s.x << 8, d.x, N);
        if (p1 < SLOTS) stg_cg32(&g_sorted[(size_t)d.y * SLOTS + p1], s.y << 8);
        else spill_edge(s.y << 8, d.y, N);
    }
    if (t == 0) {
        for (int e = E2 * 2; e < E; e++) {
            int d = tgt[e];
            int pos = atomicAdd(&g_cnt[d], 1);
            if (pos < SLOTS) stg_cg32(&g_sorted[(size_t)d * SLOTS + pos], src[e] << 8);
            else spill_edge(src[e] << 8, d, N);
        }
    }
}

__device__ __forceinline__ ull f2add(ull a, ull b) {
    ull r;
    asm("add.rn.f32x2 %0, %1, %2;" : "=l"(r) : "l"(a), "l"(b));
    return r;
}
__device__ __forceinline__ ull f2mul(ull a, ull b) {
    ull r;
    asm("mul.rn.f32x2 %0, %1, %2;" : "=l"(r) : "l"(a), "l"(b));
    return r;
}
// L2-only gather (skip L1 allocation: gathered rows have ~no per-SM reuse).
__device__ __forceinline__ ull ldg_cg64(const void* p) {
    ull r;
    asm volatile("ld.global.cg.u64 %0, [%1];" : "=l"(r) : "l"(p));
    return r;
}

// One warp per node, persistent grid-stride (one wave). Lane owns 8B (float2)
// of the 256B row. Unroll 2, one warp-uniform int2 idx load per edge pair,
// 2 accumulators (measured optimum vs L1tex queue contention).
__global__ void __launch_bounds__(256)
aggregate_kernel(const char* __restrict__ xbase,
                 float2* __restrict__ out2, int N) {
    int warp_id = (blockIdx.x * blockDim.x + threadIdx.x) >> 5;
    int lane = threadIdx.x & 31;
    int nwarps = (gridDim.x * blockDim.x) >> 5;
    const char* xlane = xbase + (lane << 3);

    for (int n = warp_id; n < N; n += nwarps) {
        int count = g_cnt[n];
        int m = count < SLOTS ? count : SLOTS;
        const int2* row2 = (const int2*)&g_sorted[(size_t)n * SLOTS];

        ull a0 = 0, a1 = 0;

        int k = 0;
        for (; k + 2 <= m; k += 2) {
            int2 s = __ldg(&row2[k >> 1]);
            ull v0 = ldg_cg64(xlane + (size_t)(unsigned)s.x);
            ull v1 = ldg_cg64(xlane + (size_t)(unsigned)s.y);
            a0 = f2add(a0, v0);
            a1 = f2add(a1, v1);
        }
        if (k < m) {
            int s = ((const int*)row2)[k];
            a0 = f2add(a0, ldg_cg64(xlane + (size_t)(unsigned)s));
        }

        // Overflow fallback (cold: only if some node's degree exceeded SLOTS).
        if (count > SLOTS) {
            int oc = g_cnt[N];
            for (int i = 0; i < oc; i++) {
                if (g_over_tgt[i] == n) {
                    int s = g_over_src[i];
                    a0 = f2add(a0, ldg_cg64(xlane + (size_t)(unsigned)s));
                }
            }
        }

        a0 = f2add(a0, a1);

        float inv = count > 0 ? 1.0f / (float)count : 0.0f;
        ull inv2;
        asm("mov.b64 %0, {%1, %1};" : "=l"(inv2) : "f"(inv));
        ull o = f2mul(a0, inv2);

        unsigned int lo, hi;
        asm("mov.b64 {%0, %1}, %2;" : "=r"(lo), "=r"(hi) : "l"(o));
        float2 ov;
        ov.x = __uint_as_float(lo);
        ov.y = __uint_as_float(hi);
        out2[(size_t)n * 32 + lane] = ov;
    }
}

extern "C" void kernel_launch(void* const* d_in, const int* in_sizes, int n_in,
                              void* d_out, int out_size) {
    const float* x = (const float*)d_in[0];
    const int* edge_idx = (const int*)d_in[1];

    int E = in_sizes[1] / 2;
    int N = out_size / F;

    const int* src = edge_idx;       // row 0
    const int* tgt = edge_idx + E;   // row 1

    // ONE memset zeroes per-node degrees AND the overflow cursor (g_cnt[N]).
    void* cnt_ptr = nullptr;
    cudaGetSymbolAddress(&cnt_ptr, g_cnt);
    cudaMemsetAsync(cnt_ptr, 0, ((size_t)N + 1) * sizeof(int));

    const int T = 256;

    int E2 = E / 2;
    int fill_blocks = (E2 + T - 1) / T;
    if (fill_blocks < 1) fill_blocks = 1;
    fill_kernel<<<fill_blocks, T>>>((const int2*)src, (const int2*)tgt, E2,
                                    src, tgt, E, N);

    // Persistent one-wave grid (cap at what N needs).
    long long warps_needed = (long long)N;
    long long blocks_needed = (warps_needed * 32 + T - 1) / T;
    int agg_blocks = blocks_needed < AGG_BLOCKS ? (int)blocks_needed : AGG_BLOCKS;
    aggregate_kernel<<<agg_blocks, T>>>((const char*)x, (float2*)d_out, N);
}

// round 17
// speedup vs baseline: 1.2897x; 1.0012x over previous
#include <cuda_runtime.h>
#include <cstdint>
#include <cstddef>

// Scatter-mean message passing via single-pass padded-CSR build + per-node gather-reduce.
//   out[t] = mean over edges e with tgt[e]==t of x[src[e]]
// x: [N, 64] f32, edge_idx: [2, E] i32 (row 0 = src, row 1 = tgt)
//
// Overflow counter lives at g_cnt[N] so ONE memset node zeroes all scratch.

#define F 64
#define MAX_N (1 << 17)      // >= 100000 (+1 slot for the overflow counter)
#define SLOTS 32             // padded CSR row capacity = 128B = one L2 line
#define MAX_OVER 16384       // overflow spill capacity (correctness fallback)
#define AGG_BLOCKS (148 * 8) // persistent grid: one wave at occ 8

typedef unsigned long long ull;

__device__ int g_cnt[MAX_N + 1];                 // [0..N): degrees; [N]: overflow cursor
__device__ int g_sorted[(size_t)MAX_N * SLOTS];  // per-node src BYTE OFFSETS (src*256)
__device__ int g_over_src[MAX_OVER];             // overflow: src byte offsets
__device__ int g_over_tgt[MAX_OVER];

__device__ __forceinline__ void spill_edge(int soff, int d, int N) {
    int op = atomicAdd(&g_cnt[N], 1);
    if (op < MAX_OVER) { g_over_src[op] = soff; g_over_tgt[op] = d; }
}

// Scattered 4B store bypassing L1 (no reuse).
__device__ __forceinline__ void stg_cg32(int* p, int v) {
    asm volatile("st.global.cg.u32 [%0], %1;" :: "l"(p), "r"(v) : "memory");
}

// Single build pass: ONE edge per thread — maximum count of independent
// atomic->store dependency chains for the L2 atomic pipeline to interleave
// (fill ladder measured: 8/thr 27us > 4/thr ~ 2/thr 19.5us; this completes it).
__global__ void fill_kernel(const int* __restrict__ src,
                            const int* __restrict__ tgt, int E, int N) {
    int e = blockIdx.x * blockDim.x + threadIdx.x;
    if (e < E) {
        int s = __ldg(&src[e]);
        int d = __ldg(&tgt[e]);
        int pos = atomicAdd(&g_cnt[d], 1);
        if (pos < SLOTS) stg_cg32(&g_sorted[(size_t)d * SLOTS + pos], s << 8);
        else spill_edge(s << 8, d, N);
    }
}

__device__ __forceinline__ ull f2add(ull a, ull b) {
    ull r;
    asm("add.rn.f32x2 %0, %1, %2;" : "=l"(r) : "l"(a), "l"(b));
    return r;
}
__device__ __forceinline__ ull f2mul(ull a, ull b) {
    ull r;
    asm("mul.rn.f32x2 %0, %1, %2;" : "=l"(r) : "l"(a), "l"(b));
    return r;
}
// L2-only gather (skip L1 allocation: gathered rows have ~no per-SM reuse).
__device__ __forceinline__ ull ldg_cg64(const void* p) {
    ull r;
    asm volatile("ld.global.cg.u64 %0, [%1];" : "=l"(r) : "l"(p));
    return r;
}

// One warp per node, persistent grid-stride (one wave). Lane owns 8B (float2)
// of the 256B row. Unroll 2, one warp-uniform int2 idx load per edge pair,
// 2 accumulators (measured optimum vs L1tex queue contention).
__global__ void __launch_bounds__(256)
aggregate_kernel(const char* __restrict__ xbase,
                 float2* __restrict__ out2, int N) {
    int warp_id = (blockIdx.x * blockDim.x + threadIdx.x) >> 5;
    int lane = threadIdx.x & 31;
    int nwarps = (gridDim.x * blockDim.x) >> 5;
    const char* xlane = xbase + (lane << 3);

    for (int n = warp_id; n < N; n += nwarps) {
        int count = g_cnt[n];
        int m = count < SLOTS ? count : SLOTS;
        const int2* row2 = (const int2*)&g_sorted[(size_t)n * SLOTS];

        ull a0 = 0, a1 = 0;

        int k = 0;
        for (; k + 2 <= m; k += 2) {
            int2 s = __ldg(&row2[k >> 1]);
            ull v0 = ldg_cg64(xlane + (size_t)(unsigned)s.x);
            ull v1 = ldg_cg64(xlane + (size_t)(unsigned)s.y);
            a0 = f2add(a0, v0);
            a1 = f2add(a1, v1);
        }
        if (k < m) {
            int s = ((const int*)row2)[k];
            a0 = f2add(a0, ldg_cg64(xlane + (size_t)(unsigned)s));
        }

        // Overflow fallback (cold: only if some node's degree exceeded SLOTS).
        if (count > SLOTS) {
            int oc = g_cnt[N];
            for (int i = 0; i < oc; i++) {
                if (g_over_tgt[i] == n) {
                    int s = g_over_src[i];
                    a0 = f2add(a0, ldg_cg64(xlane + (size_t)(unsigned)s));
                }
            }
        }

        a0 = f2add(a0, a1);

        float inv = count > 0 ? 1.0f / (float)count : 0.0f;
        ull inv2;
        asm("mov.b64 %0, {%1, %1};" : "=l"(inv2) : "f"(inv));
        ull o = f2mul(a0, inv2);

        unsigned int lo, hi;
        asm("mov.b64 {%0, %1}, %2;" : "=r"(lo), "=r"(hi) : "l"(o));
        float2 ov;
        ov.x = __uint_as_float(lo);
        ov.y = __uint_as_float(hi);
        out2[(size_t)n * 32 + lane] = ov;
    }
}

extern "C" void kernel_launch(void* const* d_in, const int* in_sizes, int n_in,
                              void* d_out, int out_size) {
    const float* x = (const float*)d_in[0];
    const int* edge_idx = (const int*)d_in[1];

    int E = in_sizes[1] / 2;
    int N = out_size / F;

    const int* src = edge_idx;       // row 0
    const int* tgt = edge_idx + E;   // row 1

    // ONE memset zeroes per-node degrees AND the overflow cursor (g_cnt[N]).
    void* cnt_ptr = nullptr;
    cudaGetSymbolAddress(&cnt_ptr, g_cnt);
    cudaMemsetAsync(cnt_ptr, 0, ((size_t)N + 1) * sizeof(int));

    const int T = 256;

    int fill_blocks = (E + T - 1) / T;
    fill_kernel<<<fill_blocks, T>>>(src, tgt, E, N);

    // Persistent one-wave grid (cap at what N needs).
    long long warps_needed = (long long)N;
    long long blocks_needed = (warps_needed * 32 + T - 1) / T;
    int agg_blocks = blocks_needed < AGG_BLOCKS ? (int)blocks_needed : AGG_BLOCKS;
    aggregate_kernel<<<agg_blocks, T>>>((const char*)x, (float2*)d_out, N);
}